// round 14
// baseline (speedup 1.0000x reference)
#include <cuda_runtime.h>

#define IMG_H 2048
#define IMG_W 2048

__global__ __launch_bounds__(256, 5)
void plane_fit_kernel(const float* __restrict__ x, float* __restrict__ out) {
    const int cx  = threadIdx.x;                       // 0..31 col-group in block
    const int gx0 = (blockIdx.x * 32 + cx) * 4;        // first of 4 owned cols
    const int gy  = blockIdx.y * 8 + threadIdx.y;      // owned output row
    const bool xint = (gx0 >= 4) && (gx0 + 7 < IMG_W);

    float4 sS = make_float4(0.f, 0.f, 0.f, 0.f);
    float4 sY = sS, sD = sS;

    // 7 input rows, 3 independent float4 loads each — no rolling state, no sync.
    #pragma unroll
    for (int j = -3; j <= 3; j++) {
        const int r = min(max(gy + j, 0), IMG_H - 1);
        const float* __restrict__ rp = x + (size_t)r * IMG_W;

        float4 a, b, c;   // cols gx0-4..gx0-1, gx0..gx0+3, gx0+4..gx0+7
        if (xint) {
            a = *reinterpret_cast<const float4*>(rp + gx0 - 4);
            b = *reinterpret_cast<const float4*>(rp + gx0);
            c = *reinterpret_cast<const float4*>(rp + gx0 + 4);
        } else {
            float f[12];
            #pragma unroll
            for (int m = 0; m < 12; m++)
                f[m] = rp[min(max(gx0 - 4 + m, 0), IMG_W - 1)];
            a = make_float4(f[0], f[1], f[2],  f[3]);
            b = make_float4(f[4], f[5], f[6],  f[7]);
            c = make_float4(f[8], f[9], f[10], f[11]);
        }

        // horizontal S (box7) and D (gradient) for the 4 columns, sliding
        float S0 = a.y + a.z + a.w + b.x + b.y + b.z + b.w;
        float S1 = S0 - a.y + c.x;
        float S2 = S1 - a.z + c.y;
        float S3 = S2 - a.w + c.z;
        float D0 = fmaf(-3.f, a.y, fmaf(-2.f, a.z,
                   fmaf( 2.f, b.z, fmaf( 3.f, b.w, b.y - a.w))));
        float D1 = fmaf(3.f, a.y, fmaf(4.f, c.x, D0 - S1));
        float D2 = fmaf(3.f, a.z, fmaf(4.f, c.y, D1 - S2));
        float D3 = fmaf(3.f, a.w, fmaf(4.f, c.z, D2 - S3));

        const float w = (float)j;
        sS.x += S0;  sS.y += S1;  sS.z += S2;  sS.w += S3;
        sY.x = fmaf(w, S0, sY.x);  sY.y = fmaf(w, S1, sY.y);
        sY.z = fmaf(w, S2, sY.z);  sY.w = fmaf(w, S3, sY.w);
        sD.x += D0;  sD.y += D1;  sD.z += D2;  sD.w += D3;
    }

    // scale + interleave (px-major: C0,C1,C2) + 3 packed float4 stores
    const float inv196 = 1.0f / 196.0f;
    const float inv49  = 1.0f / 49.0f;
    float* __restrict__ o = out + ((size_t)gy * IMG_W + gx0) * 3;
    float4 p0 = make_float4(sD.x*inv196, sY.x*inv196, sS.x*inv49, sD.y*inv196);
    float4 p1 = make_float4(sY.y*inv196, sS.y*inv49,  sD.z*inv196, sY.z*inv196);
    float4 p2 = make_float4(sS.z*inv49,  sD.w*inv196, sY.w*inv196, sS.w*inv49);
    reinterpret_cast<float4*>(o)[0] = p0;
    reinterpret_cast<float4*>(o)[1] = p1;
    reinterpret_cast<float4*>(o)[2] = p2;
}

extern "C" void kernel_launch(void* const* d_in, const int* in_sizes, int n_in,
                              void* d_out, int out_size) {
    const float* x = (const float*)d_in[0];
    float* out = (float*)d_out;
    dim3 block(32, 8);
    dim3 grid(IMG_W / 128, IMG_H / 8);   // (16, 256) = 4096 blocks
    plane_fit_kernel<<<grid, block>>>(x, out);
}

// round 15
// speedup vs baseline: 1.0111x; 1.0111x over previous
#include <cuda_runtime.h>

#define IMG_H 2048
#define IMG_W 2048

__device__ __forceinline__ float4 f4add(float4 a, float4 b) {
    return make_float4(a.x+b.x, a.y+b.y, a.z+b.z, a.w+b.w);
}
__device__ __forceinline__ float4 f4sub(float4 a, float4 b) {
    return make_float4(a.x-b.x, a.y-b.y, a.z-b.z, a.w-b.w);
}
__device__ __forceinline__ float4 f4fma(float w, float4 a, float4 acc) {
    return make_float4(fmaf(w,a.x,acc.x), fmaf(w,a.y,acc.y),
                       fmaf(w,a.z,acc.z), fmaf(w,a.w,acc.w));
}

template <bool VFAST>
__device__ __forceinline__ void body(const float* __restrict__ x,
                                     float* __restrict__ out,
                                     int gx0, int gy, bool xint) {
    float4 sS = make_float4(0.f,0.f,0.f,0.f);
    float4 sY = sS, sD = sS;
    float4 Sm3, Dm3, Sp4, Dp4;     // j=-3 (leaving) and j=+4 (entering) rows

    // 8 input rows j = -3..+4 for output rows gy, gy+1
    #pragma unroll
    for (int j = -3; j <= 4; j++) {
        const int r = VFAST ? (gy + j) : min(max(gy + j, 0), IMG_H - 1);
        const float* __restrict__ rp = x + (size_t)r * IMG_W;

        float4 a, b, c;
        if (xint) {
            a = *reinterpret_cast<const float4*>(rp + gx0 - 4);
            b = *reinterpret_cast<const float4*>(rp + gx0);
            c = *reinterpret_cast<const float4*>(rp + gx0 + 4);
        } else {
            float f[12];
            #pragma unroll
            for (int m = 0; m < 12; m++)
                f[m] = rp[min(max(gx0 - 4 + m, 0), IMG_W - 1)];
            a = make_float4(f[0], f[1], f[2],  f[3]);
            b = make_float4(f[4], f[5], f[6],  f[7]);
            c = make_float4(f[8], f[9], f[10], f[11]);
        }

        // horizontal S (box7) and D (gradient), sliding across the 4 cols
        float S0 = a.y + a.z + a.w + b.x + b.y + b.z + b.w;
        float S1 = S0 - a.y + c.x;
        float S2 = S1 - a.z + c.y;
        float S3 = S2 - a.w + c.z;
        float D0 = fmaf(-3.f, a.y, fmaf(-2.f, a.z,
                   fmaf( 2.f, b.z, fmaf( 3.f, b.w, b.y - a.w))));
        float D1 = fmaf(3.f, a.y, fmaf(4.f, c.x, D0 - S1));
        float D2 = fmaf(3.f, a.z, fmaf(4.f, c.y, D1 - S2));
        float D3 = fmaf(3.f, a.w, fmaf(4.f, c.z, D2 - S3));
        const float4 S = make_float4(S0, S1, S2, S3);
        const float4 D = make_float4(D0, D1, D2, D3);

        if (j == -3) { Sm3 = S; Dm3 = D; }
        if (j ==  4) { Sp4 = S; Dp4 = D; }
        else {
            // accumulate into out-row 0's 7-tap (j = -3..3)
            sS = f4add(sS, S);
            sY = f4fma((float)j, S, sY);
            sD = f4add(sD, D);
        }
    }

    const float inv196 = 1.0f / 196.0f;
    const float inv49  = 1.0f / 49.0f;

    // ---- store output row gy ----
    {
        float* __restrict__ o = out + ((size_t)gy * IMG_W + gx0) * 3;
        float4 p0 = make_float4(sD.x*inv196, sY.x*inv196, sS.x*inv49, sD.y*inv196);
        float4 p1 = make_float4(sY.y*inv196, sS.y*inv49,  sD.z*inv196, sY.z*inv196);
        float4 p2 = make_float4(sS.z*inv49,  sD.w*inv196, sY.w*inv196, sS.w*inv49);
        reinterpret_cast<float4*>(o)[0] = p0;
        reinterpret_cast<float4*>(o)[1] = p1;
        reinterpret_cast<float4*>(o)[2] = p2;
    }

    // ---- roll to output row gy+1:  sY' = sY - sS + 4*S(-3) + 3*S(+4) ----
    {
        float4 sY1 = f4fma(4.f, Sm3, f4fma(3.f, Sp4, f4sub(sY, sS)));
        float4 sS1 = f4add(f4sub(sS, Sm3), Sp4);
        float4 sD1 = f4add(f4sub(sD, Dm3), Dp4);

        float* __restrict__ o = out + ((size_t)(gy + 1) * IMG_W + gx0) * 3;
        float4 p0 = make_float4(sD1.x*inv196, sY1.x*inv196, sS1.x*inv49, sD1.y*inv196);
        float4 p1 = make_float4(sY1.y*inv196, sS1.y*inv49,  sD1.z*inv196, sY1.z*inv196);
        float4 p2 = make_float4(sS1.z*inv49,  sD1.w*inv196, sY1.w*inv196, sS1.w*inv49);
        reinterpret_cast<float4*>(o)[0] = p0;
        reinterpret_cast<float4*>(o)[1] = p1;
        reinterpret_cast<float4*>(o)[2] = p2;
    }
}

__global__ __launch_bounds__(128, 8)
void plane_fit_kernel(const float* __restrict__ x, float* __restrict__ out) {
    const int gx0 = (blockIdx.x * 32 + threadIdx.x) * 4;        // 4 owned cols
    const int gy  = (blockIdx.y * 4 + threadIdx.y) * 2;         // 2 owned rows
    const bool xint  = (gx0 >= 4) && (gx0 + 7 < IMG_W);
    const bool vfast = (gy >= 3) && (gy + 5 < IMG_H);           // rows gy-3..gy+4 in range

    if (vfast) body<true >(x, out, gx0, gy, xint);
    else       body<false>(x, out, gx0, gy, xint);
}

extern "C" void kernel_launch(void* const* d_in, const int* in_sizes, int n_in,
                              void* d_out, int out_size) {
    const float* x = (const float*)d_in[0];
    float* out = (float*)d_out;
    dim3 block(32, 4);                      // 128 threads: 128 cols x 8 rows tile
    dim3 grid(IMG_W / 128, IMG_H / 8);      // (16, 256) = 4096 blocks
    plane_fit_kernel<<<grid, block>>>(x, out);
}

// round 16
// speedup vs baseline: 1.1098x; 1.0976x over previous
#include <cuda_runtime.h>

#define IMG_H 2048
#define IMG_W 2048

__device__ __forceinline__ float4 f4add(float4 a, float4 b) {
    return make_float4(a.x+b.x, a.y+b.y, a.z+b.z, a.w+b.w);
}
__device__ __forceinline__ float4 f4sub(float4 a, float4 b) {
    return make_float4(a.x-b.x, a.y-b.y, a.z-b.z, a.w-b.w);
}
__device__ __forceinline__ float4 f4fma(float w, float4 a, float4 acc) {
    return make_float4(fmaf(w,a.x,acc.x), fmaf(w,a.y,acc.y),
                       fmaf(w,a.z,acc.z), fmaf(w,a.w,acc.w));
}

// Block tile: 128 cols x 16 rows. Staged output: 16 rows x 384 floats (1536 B/row).
__shared__ __align__(16) float out_s[16][384];

template <bool VFAST>
__device__ __forceinline__ void body(const float* __restrict__ x,
                                     int gx0, int gy, int lr0, int ltx, bool xint) {
    float4 sS = make_float4(0.f,0.f,0.f,0.f);
    float4 sY = sS, sD = sS;
    float4 Sm3, Dm3, Sp4, Dp4;

    // 8 input rows j = -3..+4 covering output rows gy, gy+1
    #pragma unroll
    for (int j = -3; j <= 4; j++) {
        const int r = VFAST ? (gy + j) : min(max(gy + j, 0), IMG_H - 1);
        const float* __restrict__ rp = x + (size_t)r * IMG_W;

        float4 a, b, c;
        if (xint) {
            a = *reinterpret_cast<const float4*>(rp + gx0 - 4);
            b = *reinterpret_cast<const float4*>(rp + gx0);
            c = *reinterpret_cast<const float4*>(rp + gx0 + 4);
        } else {
            float f[12];
            #pragma unroll
            for (int m = 0; m < 12; m++)
                f[m] = rp[min(max(gx0 - 4 + m, 0), IMG_W - 1)];
            a = make_float4(f[0], f[1], f[2],  f[3]);
            b = make_float4(f[4], f[5], f[6],  f[7]);
            c = make_float4(f[8], f[9], f[10], f[11]);
        }

        float S0 = a.y + a.z + a.w + b.x + b.y + b.z + b.w;
        float S1 = S0 - a.y + c.x;
        float S2 = S1 - a.z + c.y;
        float S3 = S2 - a.w + c.z;
        float D0 = fmaf(-3.f, a.y, fmaf(-2.f, a.z,
                   fmaf( 2.f, b.z, fmaf( 3.f, b.w, b.y - a.w))));
        float D1 = fmaf(3.f, a.y, fmaf(4.f, c.x, D0 - S1));
        float D2 = fmaf(3.f, a.z, fmaf(4.f, c.y, D1 - S2));
        float D3 = fmaf(3.f, a.w, fmaf(4.f, c.z, D2 - S3));
        const float4 S = make_float4(S0, S1, S2, S3);
        const float4 D = make_float4(D0, D1, D2, D3);

        if (j == -3) { Sm3 = S; Dm3 = D; }
        if (j ==  4) { Sp4 = S; Dp4 = D; }
        else {
            sS = f4add(sS, S);
            sY = f4fma((float)j, S, sY);
            sD = f4add(sD, D);
        }
    }

    const float inv196 = 1.0f / 196.0f;
    const float inv49  = 1.0f / 49.0f;

    // ---- stage output row 0 ----
    {
        float* __restrict__ o = &out_s[lr0][ltx * 12];
        reinterpret_cast<float4*>(o)[0] =
            make_float4(sD.x*inv196, sY.x*inv196, sS.x*inv49, sD.y*inv196);
        reinterpret_cast<float4*>(o)[1] =
            make_float4(sY.y*inv196, sS.y*inv49,  sD.z*inv196, sY.z*inv196);
        reinterpret_cast<float4*>(o)[2] =
            make_float4(sS.z*inv49,  sD.w*inv196, sY.w*inv196, sS.w*inv49);
    }

    // ---- roll to row 1:  sY' = sY - sS + 4*S(-3) + 3*S(+4) ----
    {
        float4 sY1 = f4fma(4.f, Sm3, f4fma(3.f, Sp4, f4sub(sY, sS)));
        float4 sS1 = f4add(f4sub(sS, Sm3), Sp4);
        float4 sD1 = f4add(f4sub(sD, Dm3), Dp4);

        float* __restrict__ o = &out_s[lr0 + 1][ltx * 12];
        reinterpret_cast<float4*>(o)[0] =
            make_float4(sD1.x*inv196, sY1.x*inv196, sS1.x*inv49, sD1.y*inv196);
        reinterpret_cast<float4*>(o)[1] =
            make_float4(sY1.y*inv196, sS1.y*inv49,  sD1.z*inv196, sY1.z*inv196);
        reinterpret_cast<float4*>(o)[2] =
            make_float4(sS1.z*inv49,  sD1.w*inv196, sY1.w*inv196, sS1.w*inv49);
    }
}

__global__ __launch_bounds__(256, 5)
void plane_fit_kernel(const float* __restrict__ x, float* __restrict__ out) {
    const int tx  = threadIdx.x;                 // 0..31
    const int ty  = threadIdx.y;                 // 0..7
    const int bx0 = blockIdx.x * 128;
    const int by0 = blockIdx.y * 16;
    const int gx0 = bx0 + tx * 4;
    const int gy  = by0 + ty * 2;                // first of 2 owned rows
    const bool xint  = (gx0 >= 4) && (gx0 + 7 < IMG_W);
    const bool vfast = (gy >= 3) && (gy + 5 < IMG_H);

    if (vfast) body<true >(x, gx0, gy, ty * 2, tx, xint);
    else       body<false>(x, gx0, gy, ty * 2, tx, xint);

    __syncthreads();

    // ---- bulk DMA: 16 rows x 1536 B, one cp.async.bulk per row, 16 issuing threads
    const int tid = ty * 32 + tx;
    if (tid < 16) {
        const int r = tid;
        float* gdst = out + ((size_t)(by0 + r) * IMG_W + bx0) * 3;
        unsigned saddr = (unsigned)__cvta_generic_to_shared(&out_s[r][0]);
        asm volatile(
            "cp.async.bulk.global.shared::cta.bulk_group [%0], [%1], %2;"
            :: "l"(gdst), "r"(saddr), "r"(1536) : "memory");
        asm volatile("cp.async.bulk.commit_group;" ::: "memory");
        asm volatile("cp.async.bulk.wait_group 0;" ::: "memory");
    }
}

extern "C" void kernel_launch(void* const* d_in, const int* in_sizes, int n_in,
                              void* d_out, int out_size) {
    const float* x = (const float*)d_in[0];
    float* out = (float*)d_out;
    dim3 block(32, 8);
    dim3 grid(IMG_W / 128, IMG_H / 16);   // (16, 128) = 2048 blocks
    plane_fit_kernel<<<grid, block>>>(x, out);
}